// round 15
// baseline (speedup 1.0000x reference)
#include <cuda_runtime.h>
#include <cstdint>
#include <math_constants.h>

#define NN   1024
#define BB   128
#define SPLITK 16
#define KS   (NN / SPLITK)   // 64 k per block
#define BK   32              // k chunk in smem
#define BM   64              // b tile
#define BN   128             // j tile
#define XS_STRIDE 68
#define NT   512             // 16 warps

// split-K partials: [SPLITK][BB][NN] = 8 MB
__device__ float g_partials[SPLITK * BB * NN];
// opaque -1.0f so ptxas cannot fold the FFMA back into FADD
__device__ float g_negone = -1.0f;

__device__ __forceinline__ void cp_async16(uint32_t dst_smem, const void* src) {
    asm volatile("cp.async.cg.shared.global [%0], [%1], 16;\n"
                 :: "r"(dst_smem), "l"(src));
}
__device__ __forceinline__ void cp_commit() {
    asm volatile("cp.async.commit_group;\n" ::: "memory");
}
__device__ __forceinline__ void cp_wait0() {
    asm volatile("cp.async.wait_group 0;\n" ::: "memory");
}

// no-op: shifts launch parity so ncu (-s 5 -c 1) captures tropical_main
__global__ void nop_kernel() {}

__global__ void __launch_bounds__(NT, 2)
tropical_main(const float* __restrict__ x,
              const float* __restrict__ w)
{
    __shared__ float xs[BK][XS_STRIDE];     // x transposed: [k][b]
    __shared__ float ws[2][BK][BN];         // w natural:    [k][j]

    const int tid = threadIdx.x;
    const int tx  = tid & 31;        // j group (0..31)
    const int ty  = tid >> 5;        // b group / warp id (0..15)
    const int j0  = blockIdx.x * BN;
    const int b0  = blockIdx.y * BM;
    const int k0  = blockIdx.z * KS;

    // x load mapping: 1 float4 per thread per chunk (64 b-rows x 32 k)
    const int xb  = tid >> 3;              // 0..63
    const int xk4 = (tid & 7) << 2;        // 0..28 step 4
    // ws load mapping: 2 cp16 per thread per chunk (32 rows x 128 j)
    const int wrow = tid >> 5;             // 0..15 (+16)
    const int wc4  = (tid & 31) << 2;      // 0..124 step 4

    const float negone = g_negone;         // runtime value -> real FFMA

    float acc[4][4];
    #pragma unroll
    for (int r = 0; r < 4; r++)
        #pragma unroll
        for (int c = 0; c < 4; c++)
            acc[r][c] = -CUDART_INF_F;

    // ---- prologue: chunk 0 -> xs + ws[0] ----
    {
        float4 xr = *reinterpret_cast<const float4*>(&x[(b0 + xb) * NN + k0 + xk4]);
        xs[xk4 + 0][xb] = xr.x;
        xs[xk4 + 1][xb] = xr.y;
        xs[xk4 + 2][xb] = xr.z;
        xs[xk4 + 3][xb] = xr.w;
        #pragma unroll
        for (int h = 0; h < 2; h++) {
            const int kr = wrow + 16 * h;
            uint32_t d = (uint32_t)__cvta_generic_to_shared(&ws[0][kr][wc4]);
            cp_async16(d, &w[(k0 + kr) * NN + j0 + wc4]);
        }
        cp_commit();
        cp_wait0();
        __syncthreads();
    }

    // ---- prefetch chunk 1: x into regs, ws via cp.async ----
    float4 xn;
    {
        const int kb = k0 + BK;
        xn = *reinterpret_cast<const float4*>(&x[(b0 + xb) * NN + kb + xk4]);
        #pragma unroll
        for (int h = 0; h < 2; h++) {
            const int kr = wrow + 16 * h;
            uint32_t d = (uint32_t)__cvta_generic_to_shared(&ws[1][kr][wc4]);
            cp_async16(d, &w[(kb + kr) * NN + j0 + wc4]);
        }
        cp_commit();
    }

    const int jq = tx << 2;   // 0..124 step 4
    const int bq = ty << 2;   // 0..60 step 4

    // ---- compute chunk 0 ----
    #pragma unroll
    for (int k = 0; k < BK; k++) {
        float4 xv = *reinterpret_cast<const float4*>(&xs[k][bq]);   // warp broadcast
        float4 wv = *reinterpret_cast<const float4*>(&ws[0][k][jq]);
        float xr4[4] = {xv.x, xv.y, xv.z, xv.w};
        float wl[4]  = {wv.x, wv.y, wv.z, wv.w};
        #pragma unroll
        for (int r = 0; r < 4; r++)
            #pragma unroll
            for (int c = 0; c < 4; c++)
                acc[r][c] = fmaxf(acc[r][c], __fmaf_rn(wl[c], negone, xr4[r]));
    }

    // ---- drain readers, stage x chunk 1 ----
    __syncthreads();
    xs[xk4 + 0][xb] = xn.x;
    xs[xk4 + 1][xb] = xn.y;
    xs[xk4 + 2][xb] = xn.z;
    xs[xk4 + 3][xb] = xn.w;
    cp_wait0();
    __syncthreads();

    // ---- compute chunk 1 ----
    #pragma unroll
    for (int k = 0; k < BK; k++) {
        float4 xv = *reinterpret_cast<const float4*>(&xs[k][bq]);
        float4 wv = *reinterpret_cast<const float4*>(&ws[1][k][jq]);
        float xr4[4] = {xv.x, xv.y, xv.z, xv.w};
        float wl[4]  = {wv.x, wv.y, wv.z, wv.w};
        #pragma unroll
        for (int r = 0; r < 4; r++)
            #pragma unroll
            for (int c = 0; c < 4; c++)
                acc[r][c] = fmaxf(acc[r][c], __fmaf_rn(wl[c], negone, xr4[r]));
    }

    // ---- write partials (plain STG.128) ----
    float* p = &g_partials[blockIdx.z * (BB * NN)];
    #pragma unroll
    for (int r = 0; r < 4; r++) {
        float4 o;
        o.x = acc[r][0]; o.y = acc[r][1]; o.z = acc[r][2]; o.w = acc[r][3];
        *reinterpret_cast<float4*>(&p[(b0 + bq + r) * NN + j0 + jq]) = o;
    }
}

__global__ void __launch_bounds__(256, 8)
tropical_reduce(const float* __restrict__ bias,
                float* __restrict__ out)
{
    const int i = (blockIdx.x * 256 + threadIdx.x) << 1;
    float2 m = *reinterpret_cast<const float2*>(&g_partials[i]);
    #pragma unroll
    for (int s = 1; s < SPLITK; s++) {
        float2 q = *reinterpret_cast<const float2*>(&g_partials[s * (BB * NN) + i]);
        m.x = fmaxf(m.x, q.x);
        m.y = fmaxf(m.y, q.y);
    }
    const int j = i & (NN - 1);
    float2 bv = *reinterpret_cast<const float2*>(&bias[j]);
    float2 o;
    o.x = m.x + bv.x;
    o.y = m.y + bv.y;
    *reinterpret_cast<float2*>(&out[i]) = o;
}

extern "C" void kernel_launch(void* const* d_in, const int* in_sizes, int n_in,
                              void* d_out, int out_size) {
    const float* x    = (const float*)d_in[0];   // [128, 1024]
    const float* wgt  = (const float*)d_in[1];   // [1024, 1024]
    const float* bias = (const float*)d_in[2];   // [1024]
    float* out = (float*)d_out;                  // [128, 1024]

    // 4 launches per call -> ncu's "-s 5 -c 1" (launch #6) hits tropical_main
    // (6 mod 4 == 2 == main's position). nops are ~free; diagnostic round.
    nop_kernel<<<1, 32>>>();

    dim3 grid(NN / BN, BB / BM, SPLITK);         // (8, 2, 16) = 256 blocks
    tropical_main<<<grid, NT>>>(x, wgt);

    const int total = BB * NN;                   // 131072
    tropical_reduce<<<total / 2 / 256, 256>>>(bias, out);  // 256 blocks

    nop_kernel<<<1, 32>>>();
}

// round 16
// speedup vs baseline: 1.0078x; 1.0078x over previous
#include <cuda_runtime.h>
#include <cstdint>
#include <math_constants.h>

#define NN   1024
#define BB   128
#define SPLITK 16
#define KS   (NN / SPLITK)   // 64 k per block
#define BK   32              // k chunk in smem
#define BM   64              // b tile
#define BN   64              // j tile
#define XS_STRIDE 68
#define NT   512             // 16 warps; 3 blocks/SM -> 12 warps/SMSP

// split-K partials: [SPLITK][BB][NN] = 8 MB
__device__ float g_partials[SPLITK * BB * NN];
// opaque -1.0f so ptxas cannot fold the FFMA back into FADD
__device__ float g_negone = -1.0f;

__device__ __forceinline__ void cp_async16(uint32_t dst_smem, const void* src) {
    asm volatile("cp.async.cg.shared.global [%0], [%1], 16;\n"
                 :: "r"(dst_smem), "l"(src));
}
__device__ __forceinline__ void cp_commit() {
    asm volatile("cp.async.commit_group;\n" ::: "memory");
}
__device__ __forceinline__ void cp_wait0() {
    asm volatile("cp.async.wait_group 0;\n" ::: "memory");
}

__global__ void __launch_bounds__(NT, 3)
tropical_main(const float* __restrict__ x,
              const float* __restrict__ w)
{
    __shared__ float xs[BK][XS_STRIDE];     // x transposed: [k][b]   8.7KB
    __shared__ float ws[2][BK][BN];         // w natural:    [k][j]  16.0KB

    const int tid = threadIdx.x;
    const int tx  = tid & 31;        // j pair index (0..31) -> 2 j each
    const int ty  = tid >> 5;        // b group / warp id (0..15) -> 4 b each
    const int j0  = blockIdx.x * BN;
    const int b0  = blockIdx.y * BM;
    const int k0  = blockIdx.z * KS;

    // x staging: 1 float4 per thread per chunk (64 b-rows x 32 k)
    const int xb  = tid >> 3;              // 0..63
    const int xk4 = (tid & 7) << 2;        // 0..28 step 4
    // ws staging: 1 cp16 per thread per chunk (32 rows x 64 j = 512 x 16B)
    const int wrow = tid >> 4;             // 0..31
    const int wc4  = (tid & 15) << 2;      // 0..60 step 4

    const float negone = g_negone;         // runtime value -> real FFMA

    float acc[4][2];
    #pragma unroll
    for (int r = 0; r < 4; r++) {
        acc[r][0] = -CUDART_INF_F;
        acc[r][1] = -CUDART_INF_F;
    }

    // ---- prologue: chunk 0 -> xs + ws[0] ----
    {
        float4 xr = *reinterpret_cast<const float4*>(&x[(b0 + xb) * NN + k0 + xk4]);
        xs[xk4 + 0][xb] = xr.x;
        xs[xk4 + 1][xb] = xr.y;
        xs[xk4 + 2][xb] = xr.z;
        xs[xk4 + 3][xb] = xr.w;
        uint32_t d = (uint32_t)__cvta_generic_to_shared(&ws[0][wrow][wc4]);
        cp_async16(d, &w[(k0 + wrow) * NN + j0 + wc4]);
        cp_commit();
        cp_wait0();
        __syncthreads();
    }

    // ---- prefetch chunk 1: x into regs, ws via cp.async ----
    float4 xn;
    {
        const int kb = k0 + BK;
        xn = *reinterpret_cast<const float4*>(&x[(b0 + xb) * NN + kb + xk4]);
        uint32_t d = (uint32_t)__cvta_generic_to_shared(&ws[1][wrow][wc4]);
        cp_async16(d, &w[(kb + wrow) * NN + j0 + wc4]);
        cp_commit();
    }

    const int jq = tx << 1;   // 0..62 step 2
    const int bq = ty << 2;   // 0..60 step 4

    // ---- compute chunk 0 ----
    #pragma unroll
    for (int k = 0; k < BK; k++) {
        float4 xv = *reinterpret_cast<const float4*>(&xs[k][bq]);   // warp broadcast
        float2 wv = *reinterpret_cast<const float2*>(&ws[0][k][jq]);
        float xr4[4] = {xv.x, xv.y, xv.z, xv.w};
        #pragma unroll
        for (int r = 0; r < 4; r++) {
            acc[r][0] = fmaxf(acc[r][0], __fmaf_rn(wv.x, negone, xr4[r]));
            acc[r][1] = fmaxf(acc[r][1], __fmaf_rn(wv.y, negone, xr4[r]));
        }
    }

    // ---- drain readers, stage x chunk 1 ----
    __syncthreads();
    xs[xk4 + 0][xb] = xn.x;
    xs[xk4 + 1][xb] = xn.y;
    xs[xk4 + 2][xb] = xn.z;
    xs[xk4 + 3][xb] = xn.w;
    cp_wait0();
    __syncthreads();

    // ---- compute chunk 1 ----
    #pragma unroll
    for (int k = 0; k < BK; k++) {
        float4 xv = *reinterpret_cast<const float4*>(&xs[k][bq]);
        float2 wv = *reinterpret_cast<const float2*>(&ws[1][k][jq]);
        float xr4[4] = {xv.x, xv.y, xv.z, xv.w};
        #pragma unroll
        for (int r = 0; r < 4; r++) {
            acc[r][0] = fmaxf(acc[r][0], __fmaf_rn(wv.x, negone, xr4[r]));
            acc[r][1] = fmaxf(acc[r][1], __fmaf_rn(wv.y, negone, xr4[r]));
        }
    }

    // ---- write partials (STG.64, coalesced 256B/warp) ----
    float* p = &g_partials[blockIdx.z * (BB * NN)];
    #pragma unroll
    for (int r = 0; r < 4; r++) {
        float2 o;
        o.x = acc[r][0];
        o.y = acc[r][1];
        *reinterpret_cast<float2*>(&p[(b0 + bq + r) * NN + j0 + jq]) = o;
    }
}

__global__ void __launch_bounds__(256, 8)
tropical_reduce(const float* __restrict__ bias,
                float* __restrict__ out)
{
    const int i = (blockIdx.x * 256 + threadIdx.x) << 1;
    float2 m = *reinterpret_cast<const float2*>(&g_partials[i]);
    #pragma unroll
    for (int s = 1; s < SPLITK; s++) {
        float2 q = *reinterpret_cast<const float2*>(&g_partials[s * (BB * NN) + i]);
        m.x = fmaxf(m.x, q.x);
        m.y = fmaxf(m.y, q.y);
    }
    const int j = i & (NN - 1);
    float2 bv = *reinterpret_cast<const float2*>(&bias[j]);
    float2 o;
    o.x = m.x + bv.x;
    o.y = m.y + bv.y;
    *reinterpret_cast<float2*>(&out[i]) = o;
}

extern "C" void kernel_launch(void* const* d_in, const int* in_sizes, int n_in,
                              void* d_out, int out_size) {
    const float* x    = (const float*)d_in[0];   // [128, 1024]
    const float* wgt  = (const float*)d_in[1];   // [1024, 1024]
    const float* bias = (const float*)d_in[2];   // [1024]
    float* out = (float*)d_out;                  // [128, 1024]

    dim3 grid(NN / BN, BB / BM, SPLITK);         // (16, 2, 16) = 512 blocks, 3/SM
    tropical_main<<<grid, NT>>>(x, wgt);

    const int total = BB * NN;                   // 131072
    tropical_reduce<<<total / 2 / 256, 256>>>(bias, out);   // 256 blocks
}

// round 17
// speedup vs baseline: 1.0094x; 1.0016x over previous
#include <cuda_runtime.h>
#include <cstdint>
#include <math_constants.h>

#define NN   1024
#define BB   128
#define SPLITK 8
#define KS   (NN / SPLITK)   // 128 k per block
#define BK   32              // k chunk in smem
#define NCH  (KS / BK)       // 4 chunks
#define BM   64              // b tile
#define BN   128             // j tile
#define XS_STRIDE 68
#define NT   1024            // 32 warps, 1 block/SM, 8 warps/SMSP

// split-K partials: [SPLITK][BB][NN] = 4 MB
__device__ float g_partials[SPLITK * BB * NN];
// opaque -1.0f so ptxas cannot fold the FFMA back into FADD
__device__ float g_negone = -1.0f;

__device__ __forceinline__ void cp_async16(uint32_t dst_smem, const void* src) {
    asm volatile("cp.async.cg.shared.global [%0], [%1], 16;\n"
                 :: "r"(dst_smem), "l"(src));
}
__device__ __forceinline__ void cp_commit() {
    asm volatile("cp.async.commit_group;\n" ::: "memory");
}
__device__ __forceinline__ void cp_wait0() {
    asm volatile("cp.async.wait_group 0;\n" ::: "memory");
}

__global__ void __launch_bounds__(NT, 1)
tropical_main(const float* __restrict__ x,
              const float* __restrict__ w)
{
    __shared__ float xs[BK][XS_STRIDE];     // x transposed: [k][b]   8.7KB
    __shared__ float ws[2][BK][BN];         // w natural:    [k][j]  32.8KB

    const int tid = threadIdx.x;
    const int tx  = tid & 31;        // j group (0..31) -> 4 j each
    const int ty  = tid >> 5;        // b group = warp id (0..31) -> 2 b each
    const int j0  = blockIdx.x * BN;
    const int b0  = blockIdx.y * BM;
    const int k0  = blockIdx.z * KS;

    // x staging: threads 0..511 move 1 float4 each per chunk (64 b x 32 k)
    const int xb  = (tid & 511) >> 3;      // 0..63
    const int xk4 = (tid & 7) << 2;        // 0..28 step 4
    const bool xload = (tid < 512);
    // ws staging: 1 cp16 per thread per chunk (32 rows x 128 j = 1024 x 16B)
    const int wrow = tid >> 5;             // 0..31
    const int wc4  = (tid & 31) << 2;      // 0..124 step 4

    const float negone = g_negone;         // runtime value -> real FFMA

    float acc[2][4];
    #pragma unroll
    for (int r = 0; r < 2; r++)
        #pragma unroll
        for (int c = 0; c < 4; c++)
            acc[r][c] = -CUDART_INF_F;

    // ---- prologue: chunk 0 -> xs + ws[0] ----
    {
        if (xload) {
            float4 xr = *reinterpret_cast<const float4*>(&x[(b0 + xb) * NN + k0 + xk4]);
            xs[xk4 + 0][xb] = xr.x;
            xs[xk4 + 1][xb] = xr.y;
            xs[xk4 + 2][xb] = xr.z;
            xs[xk4 + 3][xb] = xr.w;
        }
        uint32_t d = (uint32_t)__cvta_generic_to_shared(&ws[0][wrow][wc4]);
        cp_async16(d, &w[(k0 + wrow) * NN + j0 + wc4]);
        cp_commit();
        cp_wait0();
        __syncthreads();
    }

    const int jq = tx << 2;   // 0..124 step 4
    const int bq = ty << 1;   // 0..62 step 2

    int buf = 0;
    #pragma unroll 1
    for (int c = 0; c < NCH; c++) {
        // prefetch chunk c+1: x into regs, ws via cp.async
        float4 xn;
        const bool more = (c + 1 < NCH);
        if (more) {
            const int kb = k0 + (c + 1) * BK;
            if (xload)
                xn = *reinterpret_cast<const float4*>(&x[(b0 + xb) * NN + kb + xk4]);
            uint32_t d = (uint32_t)__cvta_generic_to_shared(&ws[buf ^ 1][wrow][wc4]);
            cp_async16(d, &w[(kb + wrow) * NN + j0 + wc4]);
            cp_commit();
        }

        // compute chunk c
        #pragma unroll
        for (int k = 0; k < BK; k++) {
            float2 xv = *reinterpret_cast<const float2*>(&xs[k][bq]);   // warp broadcast
            float4 wv = *reinterpret_cast<const float4*>(&ws[buf][k][jq]);
            float wl[4] = {wv.x, wv.y, wv.z, wv.w};
            #pragma unroll
            for (int cc = 0; cc < 4; cc++) {
                acc[0][cc] = fmaxf(acc[0][cc], __fmaf_rn(wl[cc], negone, xv.x));
                acc[1][cc] = fmaxf(acc[1][cc], __fmaf_rn(wl[cc], negone, xv.y));
            }
        }

        if (more) {
            __syncthreads();          // drain xs readers before overwrite
            if (xload) {
                xs[xk4 + 0][xb] = xn.x;
                xs[xk4 + 1][xb] = xn.y;
                xs[xk4 + 2][xb] = xn.z;
                xs[xk4 + 3][xb] = xn.w;
            }
            cp_wait0();
            __syncthreads();
        }
        buf ^= 1;
    }

    // ---- write partials (STG.128) ----
    float* p = &g_partials[blockIdx.z * (BB * NN)];
    #pragma unroll
    for (int r = 0; r < 2; r++) {
        float4 o;
        o.x = acc[r][0]; o.y = acc[r][1]; o.z = acc[r][2]; o.w = acc[r][3];
        *reinterpret_cast<float4*>(&p[(b0 + bq + r) * NN + j0 + jq]) = o;
    }
}

__global__ void __launch_bounds__(256, 8)
tropical_reduce(const float* __restrict__ bias,
                float* __restrict__ out)
{
    const int i = (blockIdx.x * 256 + threadIdx.x) << 1;
    float2 m = *reinterpret_cast<const float2*>(&g_partials[i]);
    #pragma unroll
    for (int s = 1; s < SPLITK; s++) {
        float2 q = *reinterpret_cast<const float2*>(&g_partials[s * (BB * NN) + i]);
        m.x = fmaxf(m.x, q.x);
        m.y = fmaxf(m.y, q.y);
    }
    const int j = i & (NN - 1);
    float2 bv = *reinterpret_cast<const float2*>(&bias[j]);
    float2 o;
    o.x = m.x + bv.x;
    o.y = m.y + bv.y;
    *reinterpret_cast<float2*>(&out[i]) = o;
}

extern "C" void kernel_launch(void* const* d_in, const int* in_sizes, int n_in,
                              void* d_out, int out_size) {
    const float* x    = (const float*)d_in[0];   // [128, 1024]
    const float* wgt  = (const float*)d_in[1];   // [1024, 1024]
    const float* bias = (const float*)d_in[2];   // [1024]
    float* out = (float*)d_out;                  // [128, 1024]

    dim3 grid(NN / BN, BB / BM, SPLITK);         // (8, 2, 8) = 128 blocks, 1/SM
    tropical_main<<<grid, NT>>>(x, wgt);

    const int total = BB * NN;                   // 131072
    tropical_reduce<<<total / 2 / 256, 256>>>(bias, out);   // 256 blocks
}